// round 1
// baseline (speedup 1.0000x reference)
#include <cuda_runtime.h>
#include <math.h>

#define NATOMS 4096
#define KX 14
#define KY 15
#define KZ 16
#define NGRID (KX*KY*KZ)          /* 3360 */
#define KYZ (KY*KZ)               /* 240 */
#define ALPHAF 4.985823141035867f
#define ALPHAD 4.985823141035867
#define COULOMB 138.935
#define CUT2 0.25f
#define TWO_PI 6.283185307179586f

// -------- device scratch (static, allocation-free) --------
__device__ float  g_grid[NGRID];
__device__ float2 g_cz[NGRID];    // [gx][gy][mz]
__device__ float2 g_cy[NGRID];    // [gx][my][mz]
__device__ float  g_bmod[KX+KY+KZ];
__device__ float  g_invbox[9];    // row-major inv(box)
__device__ float  g_V;
__device__ double g_edir, g_erec, g_q2;

// -------- order-5 cardinal B-spline: d[k] = M5(w+k), w in [0,1) --------
__device__ __forceinline__ void bspline5(float w, float d[5]) {
    float b2_0 = w, b2_1 = 1.0f - w;
    float b3_0 = 0.5f * w * b2_0;
    float b3_1 = 0.5f * ((w + 1.0f) * b2_1 + (2.0f - w) * b2_0);
    float b3_2 = 0.5f * (1.0f - w) * b2_1;
    const float i3 = 1.0f / 3.0f;
    float b4_0 = i3 * w * b3_0;
    float b4_1 = i3 * ((w + 1.0f) * b3_1 + (3.0f - w) * b3_0);
    float b4_2 = i3 * ((w + 2.0f) * b3_2 + (2.0f - w) * b3_1);
    float b4_3 = i3 * (1.0f - w) * b3_2;
    d[0] = 0.25f * w * b4_0;
    d[1] = 0.25f * ((w + 1.0f) * b4_1 + (4.0f - w) * b4_0);
    d[2] = 0.25f * ((w + 2.0f) * b4_2 + (3.0f - w) * b4_1);
    d[3] = 0.25f * ((w + 3.0f) * b4_3 + (2.0f - w) * b4_2);
    d[4] = 0.25f * (1.0f - w) * b4_3;
}

// -------- init: zero scratch, inv(box), V, B-spline moduli --------
__global__ void k_zero(const float* __restrict__ box) {
    int t = blockIdx.x * blockDim.x + threadIdx.x;
    for (int i = t; i < NGRID; i += gridDim.x * blockDim.x) g_grid[i] = 0.0f;
    if (t == 0) {
        g_edir = 0.0; g_erec = 0.0; g_q2 = 0.0;
        double b00 = box[0], b01 = box[1], b02 = box[2];
        double b10 = box[3], b11 = box[4], b12 = box[5];
        double b20 = box[6], b21 = box[7], b22 = box[8];
        double c00 =  (b11*b22 - b12*b21);
        double c01 = -(b10*b22 - b12*b20);
        double c02 =  (b10*b21 - b11*b20);
        double det = b00*c00 + b01*c01 + b02*c02;
        double id = 1.0 / det;
        g_invbox[0] = (float)(c00 * id);
        g_invbox[1] = (float)(-(b01*b22 - b02*b21) * id);
        g_invbox[2] = (float)( (b01*b12 - b02*b11) * id);
        g_invbox[3] = (float)(c01 * id);
        g_invbox[4] = (float)( (b00*b22 - b02*b20) * id);
        g_invbox[5] = (float)(-(b00*b12 - b02*b10) * id);
        g_invbox[6] = (float)(c02 * id);
        g_invbox[7] = (float)(-(b00*b21 - b01*b20) * id);
        g_invbox[8] = (float)( (b00*b11 - b01*b10) * id);
        g_V = (float)fabs(det);
    }
    if (t < KX + KY + KZ) {
        int K, m;
        if      (t < KX)      { K = KX; m = t; }
        else if (t < KX + KY) { K = KY; m = t - KX; }
        else                  { K = KZ; m = t - KX - KY; }
        const float Mv[4] = {1.0f/24.0f, 11.0f/24.0f, 11.0f/24.0f, 1.0f/24.0f};
        float dr = 0.0f, di = 0.0f;
        #pragma unroll
        for (int k = 0; k < 4; k++) {
            int p = (m * k) % K;
            float th = TWO_PI * (float)p / (float)K;
            float s, c; __sincosf(th, &s, &c);
            dr += Mv[k] * c; di += Mv[k] * s;
        }
        float d2 = dr*dr + di*di;
        g_bmod[t] = (d2 < 1e-7f) ? 0.0f : 1.0f / d2;
    }
}

// -------- charge spreading + sum(q^2) --------
__global__ void k_spread(const float* __restrict__ pos, const float* __restrict__ chg) {
    int i = blockIdx.x * blockDim.x + threadIdx.x;
    float q = 0.0f;
    if (i < NATOMS) {
        q = chg[i];
        float px = pos[3*i], py = pos[3*i+1], pz = pos[3*i+2];
        const int Ks[3] = {KX, KY, KZ};
        float wts[3][5];
        int   idx[3][5];
        #pragma unroll
        for (int d = 0; d < 3; d++) {
            float f = px*g_invbox[0+d] + py*g_invbox[3+d] + pz*g_invbox[6+d];
            f -= floorf(f);
            if (f >= 1.0f) f = 0.0f;
            float u  = f * (float)Ks[d];
            float fl = floorf(u);
            int base = (int)fl;
            if (base >= Ks[d]) { base = Ks[d] - 1; fl = (float)base; }
            float w = u - fl;
            bspline5(w, wts[d]);
            #pragma unroll
            for (int k = 0; k < 5; k++) {
                int ii = base - k;
                if (ii < 0) ii += Ks[d];
                idx[d][k] = ii;
            }
        }
        #pragma unroll
        for (int a = 0; a < 5; a++) {
            #pragma unroll
            for (int b = 0; b < 5; b++) {
                float wab = q * wts[0][a] * wts[1][b];
                int off = idx[0][a] * KYZ + idx[1][b] * KZ;
                #pragma unroll
                for (int c = 0; c < 5; c++)
                    atomicAdd(&g_grid[off + idx[2][c]], wab * wts[2][c]);
            }
        }
    }
    // warp-reduce q^2
    float q2 = q * q;
    #pragma unroll
    for (int o = 16; o; o >>= 1) q2 += __shfl_xor_sync(0xffffffffu, q2, o);
    if ((threadIdx.x & 31) == 0) atomicAdd(&g_q2, (double)q2);
}

// -------- DFT pass over z:  cz[gx][gy][mz] --------
__global__ void k_dftz() {
    int t = blockIdx.x * blockDim.x + threadIdx.x;
    if (t >= NGRID) return;
    int gx = t / KYZ, r = t % KYZ, gy = r / KZ, mz = r % KZ;
    const float* q = &g_grid[gx * KYZ + gy * KZ];
    float fr = 0.0f, fi = 0.0f;
    #pragma unroll
    for (int gz = 0; gz < KZ; gz++) {
        int p = (mz * gz) & (KZ - 1);
        float th = -TWO_PI * (float)p * (1.0f / (float)KZ);
        float s, c; __sincosf(th, &s, &c);
        fr += q[gz] * c; fi += q[gz] * s;
    }
    g_cz[t] = make_float2(fr, fi);
}

// -------- DFT pass over y:  cy[gx][my][mz] --------
__global__ void k_dfty() {
    int t = blockIdx.x * blockDim.x + threadIdx.x;
    if (t >= NGRID) return;
    int gx = t / KYZ, r = t % KYZ, my = r / KZ, mz = r % KZ;
    float fr = 0.0f, fi = 0.0f;
    #pragma unroll
    for (int gy = 0; gy < KY; gy++) {
        float2 cv = g_cz[gx * KYZ + gy * KZ + mz];
        int p = (my * gy) % KY;
        float th = -TWO_PI * (float)p * (1.0f / (float)KY);
        float s, c; __sincosf(th, &s, &c);
        fr += cv.x * c - cv.y * s;
        fi += cv.x * s + cv.y * c;
    }
    g_cy[t] = make_float2(fr, fi);
}

// -------- DFT pass over x + green/B reduction --------
__global__ void k_dftx(void) {
    int t = blockIdx.x * blockDim.x + threadIdx.x;   // 7 x 480 = 3360
    float contrib = 0.0f;
    if (t < NGRID) {
        int mx = t / KYZ, r = t % KYZ, my = r / KZ, mz = r % KZ;
        float fr = 0.0f, fi = 0.0f;
        #pragma unroll
        for (int gx = 0; gx < KX; gx++) {
            float2 cv = g_cy[gx * KYZ + my * KZ + mz];
            int p = (mx * gx) % KX;
            float th = -TWO_PI * (float)p * (1.0f / (float)KX);
            float s, c; __sincosf(th, &s, &c);
            fr += cv.x * c - cv.y * s;
            fi += cv.x * s + cv.y * c;
        }
        int smx = (mx <= (KX - 1) / 2) ? mx : mx - KX;
        int smy = (my <= (KY - 1) / 2) ? my : my - KY;
        int smz = (mz <= (KZ - 1) / 2) ? mz : mz - KZ;
        float fx = (float)smx, fy = (float)smy, fz = (float)smz;
        float mv0 = fx*g_invbox[0] + fy*g_invbox[1] + fz*g_invbox[2];
        float mv1 = fx*g_invbox[3] + fy*g_invbox[4] + fz*g_invbox[5];
        float mv2 = fx*g_invbox[6] + fy*g_invbox[7] + fz*g_invbox[8];
        float m2 = mv0*mv0 + mv1*mv1 + mv2*mv2;
        if (m2 > 0.0f) {
            const float pi2_over_a2 = (float)(9.869604401089358 / (ALPHAD * ALPHAD));
            float green = expf(-pi2_over_a2 * m2) / m2;
            float B = g_bmod[mx] * g_bmod[KX + my] * g_bmod[KX + KY + mz];
            contrib = green * B * (fr*fr + fi*fi);
        }
    }
    // block reduce (480 threads = 15 warps)
    __shared__ float sred[16];
    #pragma unroll
    for (int o = 16; o; o >>= 1) contrib += __shfl_xor_sync(0xffffffffu, contrib, o);
    int wid = threadIdx.x >> 5;
    if ((threadIdx.x & 31) == 0) sred[wid] = contrib;
    __syncthreads();
    if (threadIdx.x == 0) {
        float s = 0.0f;
        int nw = (blockDim.x + 31) >> 5;
        for (int w = 0; w < nw; w++) s += sred[w];
        atomicAdd(&g_erec, (double)s);
    }
}

// -------- direct space: all pairs, minimum image, erfc/r --------
__global__ void __launch_bounds__(256) k_direct(const float* __restrict__ pos,
                                                const float* __restrict__ chg,
                                                const float* __restrict__ box) {
    __shared__ float4 sj[256];
    __shared__ float sred[8];
    int tx = threadIdx.x;
    int i  = blockIdx.x * 256 + tx;
    int j0 = blockIdx.y * 256;
    int jg = j0 + tx;
    sj[tx] = make_float4(pos[3*jg], pos[3*jg+1], pos[3*jg+2], chg[jg]);
    __syncthreads();
    float Lx = box[0], Ly = box[4], Lz = box[8];
    float iLx = 1.0f / Lx, iLy = 1.0f / Ly, iLz = 1.0f / Lz;
    float xi = pos[3*i], yi = pos[3*i+1], zi = pos[3*i+2], qi = chg[i];
    float acc = 0.0f;
    #pragma unroll 4
    for (int jj = 0; jj < 256; jj++) {
        float4 p = sj[jj];
        float dx = xi - p.x; dx -= Lx * rintf(dx * iLx);
        float dy = yi - p.y; dy -= Ly * rintf(dy * iLy);
        float dz = zi - p.z; dz -= Lz * rintf(dz * iLz);
        float r2 = fmaf(dx, dx, fmaf(dy, dy, dz * dz));
        if (r2 < CUT2 && (j0 + jj) != i) {
            float rinv = rsqrtf(r2);
            float rr = r2 * rinv;
            acc += qi * p.w * erfcf(ALPHAF * rr) * rinv;
        }
    }
    #pragma unroll
    for (int o = 16; o; o >>= 1) acc += __shfl_xor_sync(0xffffffffu, acc, o);
    int wid = tx >> 5;
    if ((tx & 31) == 0) sred[wid] = acc;
    __syncthreads();
    if (tx == 0) {
        float s = 0.0f;
        #pragma unroll
        for (int w = 0; w < 8; w++) s += sred[w];
        atomicAdd(&g_edir, (double)s);
    }
}

// -------- final combine --------
__global__ void k_final(float* __restrict__ out) {
    const double SQRT_PI = 1.7724538509055159;
    double edir  = 0.5 * COULOMB * g_edir;
    double erec  = COULOMB / (2.0 * 3.141592653589793 * (double)g_V) * g_erec;
    double eself = -COULOMB * ALPHAD / SQRT_PI * g_q2;
    out[0] = (float)(edir - (erec + eself));
}

extern "C" void kernel_launch(void* const* d_in, const int* in_sizes, int n_in,
                              void* d_out, int out_size) {
    // map inputs by size (positions 12288, charges 4096, box 9)
    int ip = 0, ic = 1, ib = 2;
    for (int k = 0; k < n_in; k++) {
        if (in_sizes[k] == NATOMS * 3) ip = k;
        else if (in_sizes[k] == NATOMS) ic = k;
        else if (in_sizes[k] == 9)      ib = k;
    }
    const float* pos = (const float*)d_in[ip];
    const float* chg = (const float*)d_in[ic];
    const float* box = (const float*)d_in[ib];
    float* out = (float*)d_out;

    k_zero<<<8, 512>>>(box);
    k_spread<<<16, 256>>>(pos, chg);
    k_dftz<<<7, 480>>>();
    k_dfty<<<7, 480>>>();
    k_dftx<<<7, 480>>>();
    k_direct<<<dim3(16, 16), 256>>>(pos, chg, box);
    k_final<<<1, 1>>>(out);
}

// round 2
// speedup vs baseline: 1.1067x; 1.1067x over previous
#include <cuda_runtime.h>
#include <math.h>

#define NATOMS 4096
#define KX 14
#define KY 15
#define KZ 16
#define NGRID (KX*KY*KZ)          /* 3360 */
#define KYZ (KY*KZ)               /* 240 */
#define ALPHAF 4.985823141035867f
#define ALPHAD 4.985823141035867
#define COULOMB 138.935
#define CUT2 0.25f
#define TWO_PI 6.283185307179586f
#define NDIRBLK 136               /* 16*17/2 participating triangle blocks */

// -------- device scratch (static, allocation-free) --------
__device__ float  g_grid[NGRID];
__device__ float2 g_cz[NGRID];    // [gx][gy][mz]
__device__ float2 g_cy[NGRID];    // [gx][my][mz]
__device__ float  g_bmod[KX+KY+KZ];
__device__ float  g_invbox[9];    // row-major inv(box)
__device__ float  g_V;
__device__ double g_edir, g_erec, g_q2;
__device__ unsigned int g_done;

// -------- order-5 cardinal B-spline: d[k] = M5(w+k), w in [0,1) --------
__device__ __forceinline__ void bspline5(float w, float d[5]) {
    float b2_0 = w, b2_1 = 1.0f - w;
    float b3_0 = 0.5f * w * b2_0;
    float b3_1 = 0.5f * ((w + 1.0f) * b2_1 + (2.0f - w) * b2_0);
    float b3_2 = 0.5f * (1.0f - w) * b2_1;
    const float i3 = 1.0f / 3.0f;
    float b4_0 = i3 * w * b3_0;
    float b4_1 = i3 * ((w + 1.0f) * b3_1 + (3.0f - w) * b3_0);
    float b4_2 = i3 * ((w + 2.0f) * b3_2 + (2.0f - w) * b3_1);
    float b4_3 = i3 * (1.0f - w) * b3_2;
    d[0] = 0.25f * w * b4_0;
    d[1] = 0.25f * ((w + 1.0f) * b4_1 + (4.0f - w) * b4_0);
    d[2] = 0.25f * ((w + 2.0f) * b4_2 + (3.0f - w) * b4_1);
    d[3] = 0.25f * ((w + 3.0f) * b4_3 + (2.0f - w) * b4_2);
    d[4] = 0.25f * (1.0f - w) * b4_3;
}

// half-warp (16-lane) sum reduce; xor offsets stay within the 16-lane group
__device__ __forceinline__ float hred(float v) {
    v += __shfl_xor_sync(0xffffffffu, v, 8);
    v += __shfl_xor_sync(0xffffffffu, v, 4);
    v += __shfl_xor_sync(0xffffffffu, v, 2);
    v += __shfl_xor_sync(0xffffffffu, v, 1);
    return v;
}

// -------- init: zero scratch, inv(box), V, B-spline moduli --------
__global__ void k_zero(const float* __restrict__ box) {
    int t = blockIdx.x * blockDim.x + threadIdx.x;
    for (int i = t; i < NGRID; i += gridDim.x * blockDim.x) g_grid[i] = 0.0f;
    if (t == 0) {
        g_edir = 0.0; g_erec = 0.0; g_q2 = 0.0; g_done = 0u;
        double b00 = box[0], b01 = box[1], b02 = box[2];
        double b10 = box[3], b11 = box[4], b12 = box[5];
        double b20 = box[6], b21 = box[7], b22 = box[8];
        double c00 =  (b11*b22 - b12*b21);
        double c01 = -(b10*b22 - b12*b20);
        double c02 =  (b10*b21 - b11*b20);
        double det = b00*c00 + b01*c01 + b02*c02;
        double id = 1.0 / det;
        g_invbox[0] = (float)(c00 * id);
        g_invbox[1] = (float)(-(b01*b22 - b02*b21) * id);
        g_invbox[2] = (float)( (b01*b12 - b02*b11) * id);
        g_invbox[3] = (float)(c01 * id);
        g_invbox[4] = (float)( (b00*b22 - b02*b20) * id);
        g_invbox[5] = (float)(-(b00*b12 - b02*b10) * id);
        g_invbox[6] = (float)(c02 * id);
        g_invbox[7] = (float)(-(b00*b21 - b01*b20) * id);
        g_invbox[8] = (float)( (b00*b11 - b01*b10) * id);
        g_V = (float)fabs(det);
    }
    if (t < KX + KY + KZ) {
        int K, m;
        if      (t < KX)      { K = KX; m = t; }
        else if (t < KX + KY) { K = KY; m = t - KX; }
        else                  { K = KZ; m = t - KX - KY; }
        const float Mv[4] = {1.0f/24.0f, 11.0f/24.0f, 11.0f/24.0f, 1.0f/24.0f};
        float dr = 0.0f, di = 0.0f;
        #pragma unroll
        for (int k = 0; k < 4; k++) {
            int p = (m * k) % K;
            float th = TWO_PI * (float)p / (float)K;
            float s, c; __sincosf(th, &s, &c);
            dr += Mv[k] * c; di += Mv[k] * s;
        }
        float d2 = dr*dr + di*di;
        g_bmod[t] = (d2 < 1e-7f) ? 0.0f : 1.0f / d2;
    }
}

// -------- charge spreading + sum(q^2) --------
__global__ void k_spread(const float* __restrict__ pos, const float* __restrict__ chg) {
    int i = blockIdx.x * blockDim.x + threadIdx.x;
    float q = 0.0f;
    if (i < NATOMS) {
        q = chg[i];
        float px = pos[3*i], py = pos[3*i+1], pz = pos[3*i+2];
        const int Ks[3] = {KX, KY, KZ};
        float wts[3][5];
        int   idx[3][5];
        #pragma unroll
        for (int d = 0; d < 3; d++) {
            float f = px*g_invbox[0+d] + py*g_invbox[3+d] + pz*g_invbox[6+d];
            f -= floorf(f);
            if (f >= 1.0f) f = 0.0f;
            float u  = f * (float)Ks[d];
            float fl = floorf(u);
            int base = (int)fl;
            if (base >= Ks[d]) { base = Ks[d] - 1; fl = (float)base; }
            float w = u - fl;
            bspline5(w, wts[d]);
            #pragma unroll
            for (int k = 0; k < 5; k++) {
                int ii = base - k;
                if (ii < 0) ii += Ks[d];
                idx[d][k] = ii;
            }
        }
        #pragma unroll
        for (int a = 0; a < 5; a++) {
            #pragma unroll
            for (int b = 0; b < 5; b++) {
                float wab = q * wts[0][a] * wts[1][b];
                int off = idx[0][a] * KYZ + idx[1][b] * KZ;
                #pragma unroll
                for (int c = 0; c < 5; c++)
                    atomicAdd(&g_grid[off + idx[2][c]], wab * wts[2][c]);
            }
        }
    }
    float q2 = q * q;
    #pragma unroll
    for (int o = 16; o; o >>= 1) q2 += __shfl_xor_sync(0xffffffffu, q2, o);
    if ((threadIdx.x & 31) == 0) atomicAdd(&g_q2, (double)q2);
}

// -------- DFT pass over z: half-warp per output point --------
__global__ void __launch_bounds__(256) k_dftz() {
    int out  = blockIdx.x * 16 + (threadIdx.x >> 4);   // 210 blocks * 16 = 3360
    int lane = threadIdx.x & 15;
    int gx = out / KYZ, r = out % KYZ, gy = r / KZ, mz = r % KZ;
    float q = g_grid[gx * KYZ + gy * KZ + lane];        // lane = gz
    int p = (mz * lane) & (KZ - 1);
    float th = -TWO_PI * (float)p * (1.0f / (float)KZ);
    float s, c; __sincosf(th, &s, &c);
    float fr = hred(q * c);
    float fi = hred(q * s);
    if (lane == 0) g_cz[out] = make_float2(fr, fi);
}

// -------- DFT pass over y --------
__global__ void __launch_bounds__(256) k_dfty() {
    int out  = blockIdx.x * 16 + (threadIdx.x >> 4);
    int lane = threadIdx.x & 15;
    int gx = out / KYZ, r = out % KYZ, my = r / KZ, mz = r % KZ;
    float fr = 0.0f, fi = 0.0f;
    if (lane < KY) {
        float2 cv = g_cz[gx * KYZ + lane * KZ + mz];    // lane = gy
        int p = (my * lane) % KY;
        float th = -TWO_PI * (float)p * (1.0f / (float)KY);
        float s, c; __sincosf(th, &s, &c);
        fr = cv.x * c - cv.y * s;
        fi = cv.x * s + cv.y * c;
    }
    fr = hred(fr); fi = hred(fi);
    if (lane == 0) g_cy[out] = make_float2(fr, fi);
}

// -------- DFT pass over x + green/B reduction --------
__global__ void __launch_bounds__(256) k_dftx() {
    __shared__ float sred[16];
    int out  = blockIdx.x * 16 + (threadIdx.x >> 4);
    int lane = threadIdx.x & 15;
    int mx = out / KYZ, r = out % KYZ, my = r / KZ, mz = r % KZ;
    float fr = 0.0f, fi = 0.0f;
    if (lane < KX) {
        float2 cv = g_cy[lane * KYZ + my * KZ + mz];    // lane = gx
        int p = (mx * lane) % KX;
        float th = -TWO_PI * (float)p * (1.0f / (float)KX);
        float s, c; __sincosf(th, &s, &c);
        fr = cv.x * c - cv.y * s;
        fi = cv.x * s + cv.y * c;
    }
    fr = hred(fr); fi = hred(fi);
    float contrib = 0.0f;
    if (lane == 0) {
        int smx = (mx <= (KX - 1) / 2) ? mx : mx - KX;
        int smy = (my <= (KY - 1) / 2) ? my : my - KY;
        int smz = (mz <= (KZ - 1) / 2) ? mz : mz - KZ;
        float fx = (float)smx, fy = (float)smy, fz = (float)smz;
        float mv0 = fx*g_invbox[0] + fy*g_invbox[1] + fz*g_invbox[2];
        float mv1 = fx*g_invbox[3] + fy*g_invbox[4] + fz*g_invbox[5];
        float mv2 = fx*g_invbox[6] + fy*g_invbox[7] + fz*g_invbox[8];
        float m2 = mv0*mv0 + mv1*mv1 + mv2*mv2;
        if (m2 > 0.0f) {
            const float pi2_over_a2 = (float)(9.869604401089358 / (ALPHAD * ALPHAD));
            float green = expf(-pi2_over_a2 * m2) / m2;
            float B = g_bmod[mx] * g_bmod[KX + my] * g_bmod[KX + KY + mz];
            contrib = green * B * (fr*fr + fi*fi);
        }
        sred[threadIdx.x >> 4] = contrib;
    }
    __syncthreads();
    if (threadIdx.x == 0) {
        float s = 0.0f;
        #pragma unroll
        for (int w = 0; w < 16; w++) s += sred[w];
        atomicAdd(&g_erec, (double)s);
    }
}

// -------- direct space: triangle blocks, min-image, erfc/r; final fused --------
__global__ void __launch_bounds__(256) k_direct(const float* __restrict__ pos,
                                                const float* __restrict__ chg,
                                                const float* __restrict__ box,
                                                float* __restrict__ out) {
    int bx = blockIdx.x, by = blockIdx.y;
    if (by < bx) return;                       // triangle
    __shared__ float4 sj[256];
    __shared__ float sred[8];
    int tx = threadIdx.x;
    int i  = bx * 256 + tx;
    int j0 = by * 256;
    int jg = j0 + tx;
    sj[tx] = make_float4(pos[3*jg], pos[3*jg+1], pos[3*jg+2], chg[jg]);
    __syncthreads();
    float Lx = box[0], Ly = box[4], Lz = box[8];
    float iLx = 1.0f / Lx, iLy = 1.0f / Ly, iLz = 1.0f / Lz;
    float xi = pos[3*i], yi = pos[3*i+1], zi = pos[3*i+2], qi = chg[i];
    float acc = 0.0f;
    if (bx == by) {
        #pragma unroll 8
        for (int jj = 0; jj < 256; jj++) {
            float4 p = sj[jj];
            float dx = xi - p.x; dx -= Lx * rintf(dx * iLx);
            float dy = yi - p.y; dy -= Ly * rintf(dy * iLy);
            float dz = zi - p.z; dz -= Lz * rintf(dz * iLz);
            float r2 = fmaf(dx, dx, fmaf(dy, dy, dz * dz));
            if (r2 < CUT2 && jj != tx) {
                float rinv = rsqrtf(r2);
                acc += qi * p.w * erfcf(ALPHAF * r2 * rinv) * rinv;
            }
        }
    } else {
        #pragma unroll 8
        for (int jj = 0; jj < 256; jj++) {
            float4 p = sj[jj];
            float dx = xi - p.x; dx -= Lx * rintf(dx * iLx);
            float dy = yi - p.y; dy -= Ly * rintf(dy * iLy);
            float dz = zi - p.z; dz -= Lz * rintf(dz * iLz);
            float r2 = fmaf(dx, dx, fmaf(dy, dy, dz * dz));
            if (r2 < CUT2) {
                float rinv = rsqrtf(r2);
                acc += qi * p.w * erfcf(ALPHAF * r2 * rinv) * rinv;
            }
        }
        acc *= 2.0f;                           // each unordered pair once
    }
    #pragma unroll
    for (int o = 16; o; o >>= 1) acc += __shfl_xor_sync(0xffffffffu, acc, o);
    int wid = tx >> 5;
    if ((tx & 31) == 0) sred[wid] = acc;
    __syncthreads();
    if (tx == 0) {
        float s = 0.0f;
        #pragma unroll
        for (int w = 0; w < 8; w++) s += sred[w];
        atomicAdd(&g_edir, (double)s);
        __threadfence();
        unsigned int done = atomicAdd(&g_done, 1u);
        if (done == NDIRBLK - 1) {             // last triangle block: combine
            const double SQRT_PI = 1.7724538509055159;
            double edir  = 0.5 * COULOMB * g_edir;
            double erec  = COULOMB / (2.0 * 3.141592653589793 * (double)g_V) * g_erec;
            double eself = -COULOMB * ALPHAD / SQRT_PI * g_q2;
            out[0] = (float)(edir - (erec + eself));
        }
    }
}

extern "C" void kernel_launch(void* const* d_in, const int* in_sizes, int n_in,
                              void* d_out, int out_size) {
    int ip = 0, ic = 1, ib = 2;
    for (int k = 0; k < n_in; k++) {
        if (in_sizes[k] == NATOMS * 3) ip = k;
        else if (in_sizes[k] == NATOMS) ic = k;
        else if (in_sizes[k] == 9)      ib = k;
    }
    const float* pos = (const float*)d_in[ip];
    const float* chg = (const float*)d_in[ic];
    const float* box = (const float*)d_in[ib];
    float* out = (float*)d_out;

    k_zero<<<8, 512>>>(box);
    k_spread<<<16, 256>>>(pos, chg);
    k_dftz<<<210, 256>>>();
    k_dfty<<<210, 256>>>();
    k_dftx<<<210, 256>>>();
    k_direct<<<dim3(16, 16), 256>>>(pos, chg, box, out);
}

// round 4
// speedup vs baseline: 1.2995x; 1.1742x over previous
#include <cuda_runtime.h>
#include <math.h>

#define NATOMS 4096
#define KX 14
#define KY 15
#define KZ 16
#define NGRID (KX*KY*KZ)          /* 3360 */
#define KYZ (KY*KZ)               /* 240 */
#define ALPHAF 4.985823141035867f
#define ALPHAD 4.985823141035867
#define COULOMB 138.935
#define CUT2 0.25f
#define NBLK 148                  /* one block per SM: all resident, spin-safe */
#define NDIRBLK 136               /* 16*17/2 triangle tiles */

// -------- device scratch (static, allocation-free) --------
__device__ float  g_grid[NGRID];
__device__ float2 g_cz[NGRID];
__device__ float2 g_cy[NGRID];
__device__ double g_edir, g_erec, g_q2;
__device__ unsigned int g_bar_count;   // zero-init
__device__ unsigned int g_bar_gen;     // zero-init, monotonically grows across replays

// -------- device-wide barrier (all NBLK blocks resident) --------
__device__ __forceinline__ void gridbar() {
    __syncthreads();
    if (threadIdx.x == 0) {
        __threadfence();
        unsigned gen = *(volatile unsigned*)&g_bar_gen;
        if (atomicAdd(&g_bar_count, 1u) == NBLK - 1) {
            *(volatile unsigned*)&g_bar_count = 0;
            __threadfence();
            *(volatile unsigned*)&g_bar_gen = gen + 1;
        } else {
            while (*(volatile unsigned*)&g_bar_gen == gen) __nanosleep(32);
        }
        __threadfence();
    }
    __syncthreads();
}

// -------- order-5 cardinal B-spline: d[k] = M5(w+k), w in [0,1) --------
__device__ __forceinline__ void bspline5(float w, float d[5]) {
    float b2_0 = w, b2_1 = 1.0f - w;
    float b3_0 = 0.5f * w * b2_0;
    float b3_1 = 0.5f * ((w + 1.0f) * b2_1 + (2.0f - w) * b2_0);
    float b3_2 = 0.5f * (1.0f - w) * b2_1;
    const float i3 = 1.0f / 3.0f;
    float b4_0 = i3 * w * b3_0;
    float b4_1 = i3 * ((w + 1.0f) * b3_1 + (3.0f - w) * b3_0);
    float b4_2 = i3 * ((w + 2.0f) * b3_2 + (2.0f - w) * b3_1);
    float b4_3 = i3 * (1.0f - w) * b3_2;
    d[0] = 0.25f * w * b4_0;
    d[1] = 0.25f * ((w + 1.0f) * b4_1 + (4.0f - w) * b4_0);
    d[2] = 0.25f * ((w + 2.0f) * b4_2 + (3.0f - w) * b4_1);
    d[3] = 0.25f * ((w + 3.0f) * b4_3 + (2.0f - w) * b4_2);
    d[4] = 0.25f * (1.0f - w) * b4_3;
}

__global__ void __launch_bounds__(256) k_all(const float* __restrict__ pos,
                                             const float* __restrict__ chg,
                                             const float* __restrict__ box,
                                             float* __restrict__ out) {
    // twiddle/bmod layout: [x: 0..13][y: 14..28][z: 29..44]
    __shared__ float  s_twc[45], s_tws[45], s_bmod[45];
    __shared__ float  s_inv[9];
    __shared__ double s_Vd;
    __shared__ float4 sj[256];
    __shared__ float  sred[8];

    const int gid = blockIdx.x;
    const int tid = threadIdx.x;
    const int lane = tid & 31;

    // ---------------- phase 0: zero mesh + tables ----------------
    {
        int gtid = gid * 256 + tid;
        if (gtid < NGRID) g_grid[gtid] = 0.0f;
        if (gid == 0 && tid == 0) { g_edir = 0.0; g_erec = 0.0; g_q2 = 0.0; }
        if (tid < 45) {
            int K, m;
            if      (tid < KX)      { K = KX; m = tid; }
            else if (tid < KX + KY) { K = KY; m = tid - KX; }
            else                    { K = KZ; m = tid - KX - KY; }
            float s, c;
            sincospif(2.0f * (float)m / (float)K, &s, &c);
            s_twc[tid] = c; s_tws[tid] = s;
            const float Mv[4] = {1.0f/24.0f, 11.0f/24.0f, 11.0f/24.0f, 1.0f/24.0f};
            float dr = 0.0f, di = 0.0f;
            #pragma unroll
            for (int k = 0; k < 4; k++) {
                int p = (m * k) % K;
                float ss, cc;
                sincospif(2.0f * (float)p / (float)K, &ss, &cc);
                dr += Mv[k] * cc; di += Mv[k] * ss;
            }
            float d2 = dr*dr + di*di;
            s_bmod[tid] = (d2 < 1e-7f) ? 0.0f : 1.0f / d2;
        }
        if (tid == 0) {
            double b00 = box[0], b01 = box[1], b02 = box[2];
            double b10 = box[3], b11 = box[4], b12 = box[5];
            double b20 = box[6], b21 = box[7], b22 = box[8];
            double c00 =  (b11*b22 - b12*b21);
            double c01 = -(b10*b22 - b12*b20);
            double c02 =  (b10*b21 - b11*b20);
            double det = b00*c00 + b01*c01 + b02*c02;
            double id = 1.0 / det;
            s_inv[0] = (float)(c00 * id);
            s_inv[1] = (float)(-(b01*b22 - b02*b21) * id);
            s_inv[2] = (float)( (b01*b12 - b02*b11) * id);
            s_inv[3] = (float)(c01 * id);
            s_inv[4] = (float)( (b00*b22 - b02*b20) * id);
            s_inv[5] = (float)(-(b00*b12 - b02*b10) * id);
            s_inv[6] = (float)(c02 * id);
            s_inv[7] = (float)(-(b00*b21 - b01*b20) * id);
            s_inv[8] = (float)( (b00*b11 - b01*b10) * id);
            s_Vd = fabs(det);
        }
    }
    gridbar();   // mesh zeroed, tables ready

    // ---------------- phase 1: spread + q^2 (warp 0 only) ----------------
    if (tid < 32) {
        int a = gid + NBLK * lane;               // unique atom per (block,lane)
        bool act = (a < NATOMS);
        float q = act ? chg[a] : 0.0f;
        if (act) {
            float px = pos[3*a], py = pos[3*a+1], pz = pos[3*a+2];
            const int Ks[3] = {KX, KY, KZ};
            float wts[3][5];
            int   idx[3][5];
            #pragma unroll
            for (int d = 0; d < 3; d++) {
                float f = px*s_inv[0+d] + py*s_inv[3+d] + pz*s_inv[6+d];
                f -= floorf(f);
                if (f >= 1.0f) f = 0.0f;
                float u  = f * (float)Ks[d];
                float fl = floorf(u);
                int base = (int)fl;
                if (base >= Ks[d]) { base = Ks[d] - 1; fl = (float)base; }
                float w = u - fl;
                bspline5(w, wts[d]);
                #pragma unroll
                for (int k = 0; k < 5; k++) {
                    int ii = base - k;
                    if (ii < 0) ii += Ks[d];
                    idx[d][k] = ii;
                }
            }
            #pragma unroll
            for (int aa = 0; aa < 5; aa++) {
                #pragma unroll
                for (int bb = 0; bb < 5; bb++) {
                    float wab = q * wts[0][aa] * wts[1][bb];
                    int off = idx[0][aa] * KYZ + idx[1][bb] * KZ;
                    #pragma unroll
                    for (int cc = 0; cc < 5; cc++)
                        atomicAdd(&g_grid[off + idx[2][cc]], wab * wts[2][cc]);
                }
            }
        }
        float q2 = q * q;
        #pragma unroll
        for (int o = 16; o; o >>= 1) q2 += __shfl_xor_sync(0xffffffffu, q2, o);
        if (lane == 0 && q2 != 0.0f) atomicAdd(&g_q2, (double)q2);
    }
    gridbar();   // mesh + q2 complete

    // ---------------- phase 2: DFT over z (warp 0) ----------------
    if (tid < 32) {
        int o = gid + NBLK * lane;
        if (o < NGRID) {
            int gx = o / KYZ, r = o % KYZ, gy = r / KZ, mz = r % KZ;
            const float* q = &g_grid[gx * KYZ + gy * KZ];
            float fr = 0.0f, fi = 0.0f;
            #pragma unroll
            for (int gz = 0; gz < KZ; gz++) {
                int p = (mz * gz) & (KZ - 1);
                float c = s_twc[29 + p], s = s_tws[29 + p];
                float v = q[gz];
                fr = fmaf(v, c, fr);
                fi = fmaf(v, -s, fi);
            }
            g_cz[o] = make_float2(fr, fi);
        }
    }
    gridbar();

    // ---------------- phase 3: DFT over y (warp 0) ----------------
    if (tid < 32) {
        int o = gid + NBLK * lane;
        if (o < NGRID) {
            int gx = o / KYZ, r = o % KYZ, my = r / KZ, mz = r % KZ;
            float fr = 0.0f, fi = 0.0f;
            #pragma unroll
            for (int gy = 0; gy < KY; gy++) {
                float2 cv = g_cz[gx * KYZ + gy * KZ + mz];
                int p = (my * gy) % KY;
                float c = s_twc[14 + p], s = s_tws[14 + p];
                // (a+bi)(c-si) = (ac+bs) + (bc-as)i
                fr += cv.x * c + cv.y * s;
                fi += cv.y * c - cv.x * s;
            }
            g_cy[o] = make_float2(fr, fi);
        }
    }
    gridbar();

    // ---------------- phase 4: DFT over x + green/B reduce (warp 0) ----------------
    if (tid < 32) {
        int o = gid + NBLK * lane;
        float contrib = 0.0f;
        if (o < NGRID) {
            int mx = o / KYZ, r = o % KYZ, my = r / KZ, mz = r % KZ;
            float fr = 0.0f, fi = 0.0f;
            #pragma unroll
            for (int gx = 0; gx < KX; gx++) {
                float2 cv = g_cy[gx * KYZ + my * KZ + mz];
                int p = (mx * gx) % KX;
                float c = s_twc[p], s = s_tws[p];
                fr += cv.x * c + cv.y * s;
                fi += cv.y * c - cv.x * s;
            }
            int smx = (mx <= (KX - 1) / 2) ? mx : mx - KX;
            int smy = (my <= (KY - 1) / 2) ? my : my - KY;
            int smz = (mz <= (KZ - 1) / 2) ? mz : mz - KZ;
            float fx = (float)smx, fy = (float)smy, fz = (float)smz;
            float mv0 = fx*s_inv[0] + fy*s_inv[1] + fz*s_inv[2];
            float mv1 = fx*s_inv[3] + fy*s_inv[4] + fz*s_inv[5];
            float mv2 = fx*s_inv[6] + fy*s_inv[7] + fz*s_inv[8];
            float m2 = mv0*mv0 + mv1*mv1 + mv2*mv2;
            if (m2 > 0.0f) {
                const float pi2_over_a2 = (float)(9.869604401089358 / (ALPHAD * ALPHAD));
                float green = __expf(-pi2_over_a2 * m2) / m2;
                float B = s_bmod[mx] * s_bmod[14 + my] * s_bmod[29 + mz];
                contrib = green * B * (fr*fr + fi*fi);
            }
        }
        #pragma unroll
        for (int o2 = 16; o2; o2 >>= 1) contrib += __shfl_xor_sync(0xffffffffu, contrib, o2);
        if (lane == 0 && contrib != 0.0f) atomicAdd(&g_erec, (double)contrib);
    }
    // no barrier needed before direct (independent data); barrier comes after

    // ---------------- phase 5: direct space triangle tile ----------------
    if (gid < NDIRBLK) {
        // decode triangle (bx, by) with by >= bx from linear gid
        int L = gid, bx = 0;
        while (L >= 16 - bx) { L -= 16 - bx; bx++; }
        int by = bx + L;

        int i  = bx * 256 + tid;
        int j0 = by * 256;
        int jg = j0 + tid;
        sj[tid] = make_float4(pos[3*jg], pos[3*jg+1], pos[3*jg+2], chg[jg]);
        __syncthreads();
        float Lx = box[0], Ly = box[4], Lz = box[8];
        float iLx = 1.0f / Lx, iLy = 1.0f / Ly, iLz = 1.0f / Lz;
        float xi = pos[3*i], yi = pos[3*i+1], zi = pos[3*i+2], qi = chg[i];
        float acc = 0.0f;
        if (bx == by) {
            #pragma unroll 8
            for (int jj = 0; jj < 256; jj++) {
                float4 p = sj[jj];
                float dx = xi - p.x; dx -= Lx * rintf(dx * iLx);
                float dy = yi - p.y; dy -= Ly * rintf(dy * iLy);
                float dz = zi - p.z; dz -= Lz * rintf(dz * iLz);
                float r2 = fmaf(dx, dx, fmaf(dy, dy, dz * dz));
                if (r2 < CUT2 && jj != tid) {
                    float rinv = rsqrtf(r2);
                    acc += qi * p.w * erfcf(ALPHAF * r2 * rinv) * rinv;
                }
            }
        } else {
            #pragma unroll 8
            for (int jj = 0; jj < 256; jj++) {
                float4 p = sj[jj];
                float dx = xi - p.x; dx -= Lx * rintf(dx * iLx);
                float dy = yi - p.y; dy -= Ly * rintf(dy * iLy);
                float dz = zi - p.z; dz -= Lz * rintf(dz * iLz);
                float r2 = fmaf(dx, dx, fmaf(dy, dy, dz * dz));
                if (r2 < CUT2) {
                    float rinv = rsqrtf(r2);
                    acc += qi * p.w * erfcf(ALPHAF * r2 * rinv) * rinv;
                }
            }
            acc *= 2.0f;   // unordered off-diagonal pairs counted once
        }
        #pragma unroll
        for (int o = 16; o; o >>= 1) acc += __shfl_xor_sync(0xffffffffu, acc, o);
        if ((tid & 31) == 0) sred[tid >> 5] = acc;
        __syncthreads();
        if (tid == 0) {
            float s = 0.0f;
            #pragma unroll
            for (int w = 0; w < 8; w++) s += sred[w];
            atomicAdd(&g_edir, (double)s);
        }
    }
    gridbar();   // all energy terms complete

    // ---------------- final combine ----------------
    if (gid == 0 && tid == 0) {
        const double SQRT_PI = 1.7724538509055159;
        double edir  = 0.5 * COULOMB * g_edir;
        double erec  = COULOMB / (2.0 * 3.141592653589793 * s_Vd) * g_erec;
        double eself = -COULOMB * ALPHAD / SQRT_PI * g_q2;
        out[0] = (float)(edir - (erec + eself));
    }
}

extern "C" void kernel_launch(void* const* d_in, const int* in_sizes, int n_in,
                              void* d_out, int out_size) {
    int ip = 0, ic = 1, ib = 2;
    for (int k = 0; k < n_in; k++) {
        if (in_sizes[k] == NATOMS * 3) ip = k;
        else if (in_sizes[k] == NATOMS) ic = k;
        else if (in_sizes[k] == 9)      ib = k;
    }
    const float* pos = (const float*)d_in[ip];
    const float* chg = (const float*)d_in[ic];
    const float* box = (const float*)d_in[ib];
    float* out = (float*)d_out;

    k_all<<<NBLK, 256>>>(pos, chg, box, out);
}

// round 9
// speedup vs baseline: 1.5397x; 1.1848x over previous
#include <cuda_runtime.h>
#include <math.h>

#define NATOMS 4096
#define KX 14
#define KY 15
#define KZ 16
#define NGRID (KX*KY*KZ)          /* 3360 */
#define KYZ (KY*KZ)               /* 240 */
#define ALPHAF 4.985823141035867f
#define ALPHAD 4.985823141035867
#define COULOMB 138.935
#define CUT2 0.25f
#define NBLK 148                  /* one block per SM: all resident, spin-safe */
#define NDIRBLK 136               /* 16*17/2 triangle tiles */
#define NTHR 1024

// -------- device scratch (static, allocation-free) --------
__device__ float  g_grid[NGRID];
__device__ float2 g_cz[NGRID];
__device__ float2 g_cy[NGRID];
__device__ double g_edir, g_erec, g_q2;
__device__ unsigned int g_bar_count;   // zero-init
__device__ unsigned int g_bar_gen;     // zero-init, grows across replays

// -------- device-wide barrier (all NBLK blocks resident) --------
__device__ __forceinline__ void gridbar() {
    __syncthreads();
    if (threadIdx.x == 0) {
        __threadfence();
        unsigned gen = *(volatile unsigned*)&g_bar_gen;
        if (atomicAdd(&g_bar_count, 1u) == NBLK - 1) {
            *(volatile unsigned*)&g_bar_count = 0;
            __threadfence();
            *(volatile unsigned*)&g_bar_gen = gen + 1;
        } else {
            while (*(volatile unsigned*)&g_bar_gen == gen) __nanosleep(32);
        }
        __threadfence();
    }
    __syncthreads();
}

// -------- order-5 cardinal B-spline: d[k] = M5(w+k), w in [0,1) --------
__device__ __forceinline__ void bspline5(float w, float d[5]) {
    float b2_0 = w, b2_1 = 1.0f - w;
    float b3_0 = 0.5f * w * b2_0;
    float b3_1 = 0.5f * ((w + 1.0f) * b2_1 + (2.0f - w) * b2_0);
    float b3_2 = 0.5f * (1.0f - w) * b2_1;
    const float i3 = 1.0f / 3.0f;
    float b4_0 = i3 * w * b3_0;
    float b4_1 = i3 * ((w + 1.0f) * b3_1 + (3.0f - w) * b3_0);
    float b4_2 = i3 * ((w + 2.0f) * b3_2 + (2.0f - w) * b3_1);
    float b4_3 = i3 * (1.0f - w) * b3_2;
    d[0] = 0.25f * w * b4_0;
    d[1] = 0.25f * ((w + 1.0f) * b4_1 + (4.0f - w) * b4_0);
    d[2] = 0.25f * ((w + 2.0f) * b4_2 + (3.0f - w) * b4_1);
    d[3] = 0.25f * ((w + 3.0f) * b4_3 + (2.0f - w) * b4_2);
    d[4] = 0.25f * (1.0f - w) * b4_3;
}

// 16-lane sum reduce. MUST be executed by all 32 lanes of every warp that
// reaches it (warp-collective); callers pass 0 for inactive lanes.
__device__ __forceinline__ float hred(float v) {
    v += __shfl_xor_sync(0xffffffffu, v, 8);
    v += __shfl_xor_sync(0xffffffffu, v, 4);
    v += __shfl_xor_sync(0xffffffffu, v, 2);
    v += __shfl_xor_sync(0xffffffffu, v, 1);
    return v;
}

__global__ void __launch_bounds__(NTHR) k_all(const float* __restrict__ pos,
                                              const float* __restrict__ chg,
                                              const float* __restrict__ box,
                                              float* __restrict__ out) {
    __shared__ float  s_twc[45], s_tws[45], s_bmod[45];
    __shared__ float  s_inv[9];
    __shared__ double s_Vd;
    __shared__ float4 sj[256];
    __shared__ float  sred[64];

    const int gid = blockIdx.x;
    const int tid = threadIdx.x;
    const int lane = tid & 31;
    const int wid = tid >> 5;

    // ---------------- phase 0: zero mesh + tables ----------------
    {
        int gtid = gid * NTHR + tid;
        if (gtid < NGRID) g_grid[gtid] = 0.0f;
        if (gid == 0 && tid == 0) { g_edir = 0.0; g_erec = 0.0; g_q2 = 0.0; }
        if (tid < 45) {
            int K, m;
            if      (tid < KX)      { K = KX; m = tid; }
            else if (tid < KX + KY) { K = KY; m = tid - KX; }
            else                    { K = KZ; m = tid - KX - KY; }
            float s, c;
            sincospif(2.0f * (float)m / (float)K, &s, &c);
            s_twc[tid] = c; s_tws[tid] = s;
            const float Mv[4] = {1.0f/24.0f, 11.0f/24.0f, 11.0f/24.0f, 1.0f/24.0f};
            float dr = 0.0f, di = 0.0f;
            #pragma unroll
            for (int k = 0; k < 4; k++) {
                int p = (m * k) % K;
                float ss, cc;
                sincospif(2.0f * (float)p / (float)K, &ss, &cc);
                dr += Mv[k] * cc; di += Mv[k] * ss;
            }
            float d2 = dr*dr + di*di;
            s_bmod[tid] = (d2 < 1e-7f) ? 0.0f : 1.0f / d2;
        }
        if (tid == 64) {   // separate warp from table warp
            double b00 = box[0], b01 = box[1], b02 = box[2];
            double b10 = box[3], b11 = box[4], b12 = box[5];
            double b20 = box[6], b21 = box[7], b22 = box[8];
            double c00 =  (b11*b22 - b12*b21);
            double c01 = -(b10*b22 - b12*b20);
            double c02 =  (b10*b21 - b11*b20);
            double det = b00*c00 + b01*c01 + b02*c02;
            double id = 1.0 / det;
            s_inv[0] = (float)(c00 * id);
            s_inv[1] = (float)(-(b01*b22 - b02*b21) * id);
            s_inv[2] = (float)( (b01*b12 - b02*b11) * id);
            s_inv[3] = (float)(c01 * id);
            s_inv[4] = (float)( (b00*b22 - b02*b20) * id);
            s_inv[5] = (float)(-(b00*b12 - b02*b10) * id);
            s_inv[6] = (float)(c02 * id);
            s_inv[7] = (float)(-(b00*b21 - b01*b20) * id);
            s_inv[8] = (float)( (b00*b11 - b01*b10) * id);
            s_Vd = fabs(det);
        }
    }
    gridbar();   // mesh zeroed, tables ready

    // ------- phase 1: spread (thread = atom x x-slice) + q^2 -------
    {
        float q2c = 0.0f;
        int k  = tid / 5;              // atom ordinal within block
        int aa = tid - 5 * k;          // x-slice 0..4
        int a  = gid + NBLK * k;
        if (a < NATOMS) {
            float q = chg[a];
            if (aa == 0) q2c = q * q;
            float px = pos[3*a], py = pos[3*a+1], pz = pos[3*a+2];
            const int Ks[3] = {KX, KY, KZ};
            float wts[3][5];
            int   idx[3][5];
            #pragma unroll
            for (int d = 0; d < 3; d++) {
                float f = px*s_inv[0+d] + py*s_inv[3+d] + pz*s_inv[6+d];
                f -= floorf(f);
                if (f >= 1.0f) f = 0.0f;
                float u  = f * (float)Ks[d];
                float fl = floorf(u);
                int base = (int)fl;
                if (base >= Ks[d]) { base = Ks[d] - 1; fl = (float)base; }
                float w = u - fl;
                bspline5(w, wts[d]);
                #pragma unroll
                for (int kk = 0; kk < 5; kk++) {
                    int ii = base - kk;
                    if (ii < 0) ii += Ks[d];
                    idx[d][kk] = ii;
                }
            }
            int offx = idx[0][aa] * KYZ;
            float wx = q * wts[0][aa];
            #pragma unroll
            for (int bb = 0; bb < 5; bb++) {
                float wab = wx * wts[1][bb];
                int off = offx + idx[1][bb] * KZ;
                #pragma unroll
                for (int cc = 0; cc < 5; cc++)
                    atomicAdd(&g_grid[off + idx[2][cc]], wab * wts[2][cc]);
            }
        }
        // full-warp reduce (all lanes participate)
        #pragma unroll
        for (int o = 16; o; o >>= 1) q2c += __shfl_xor_sync(0xffffffffu, q2c, o);
        if (lane == 0) sred[wid] = q2c;
        __syncthreads();
        if (tid == 0) {
            float s = 0.0f;
            #pragma unroll
            for (int w = 0; w < 32; w++) s += sred[w];
            if (s != 0.0f) atomicAdd(&g_q2, (double)s);
        }
    }
    gridbar();   // mesh + q2 complete

    // ------- phase 2: DFT over z (16-lane group per output) -------
    {
        int grp = tid >> 4, l = tid & 15;
        int o = gid + NBLK * grp;             // bijective over [0, 148*64)
        bool ok = (o < NGRID);
        float vc = 0.0f, vs = 0.0f;
        if (ok) {
            int gx = o / KYZ, r = o % KYZ, gy = r / KZ, mz = r % KZ;
            float v = g_grid[gx * KYZ + gy * KZ + l];    // l = gz
            int p = (mz * l) & (KZ - 1);
            vc =  v * s_twc[29 + p];
            vs = -v * s_tws[29 + p];
        }
        float fr = hred(vc);                  // warp-collective: all lanes
        float fi = hred(vs);
        if (ok && l == 0) g_cz[o] = make_float2(fr, fi);
    }
    gridbar();

    // ------- phase 3: DFT over y -------
    {
        int grp = tid >> 4, l = tid & 15;
        int o = gid + NBLK * grp;
        bool ok = (o < NGRID);
        float fr = 0.0f, fi = 0.0f;
        if (ok && l < KY) {
            int gx = o / KYZ, r = o % KYZ, my = r / KZ, mz = r % KZ;
            float2 cv = g_cz[gx * KYZ + l * KZ + mz];   // l = gy
            int p = (my * l) % KY;
            float c = s_twc[14 + p], s = s_tws[14 + p];
            fr = cv.x * c + cv.y * s;
            fi = cv.y * c - cv.x * s;
        }
        fr = hred(fr); fi = hred(fi);         // warp-collective: all lanes
        if (ok && l == 0) g_cy[o] = make_float2(fr, fi);
    }
    gridbar();

    // ------- phase 4: DFT over x + green/B reduce -------
    {
        int grp = tid >> 4, l = tid & 15;
        int o = gid + NBLK * grp;
        bool ok = (o < NGRID);
        float fr = 0.0f, fi = 0.0f;
        int mx = 0, my = 0, mz = 0;
        if (ok) {
            mx = o / KYZ; int r = o % KYZ; my = r / KZ; mz = r % KZ;
            if (l < KX) {
                float2 cv = g_cy[l * KYZ + my * KZ + mz];   // l = gx
                int p = (mx * l) % KX;
                float c = s_twc[p], s = s_tws[p];
                fr = cv.x * c + cv.y * s;
                fi = cv.y * c - cv.x * s;
            }
        }
        fr = hred(fr); fi = hred(fi);         // warp-collective: all lanes
        float contrib = 0.0f;
        if (ok && l == 0) {
            int smx = (mx <= (KX - 1) / 2) ? mx : mx - KX;
            int smy = (my <= (KY - 1) / 2) ? my : my - KY;
            int smz = (mz <= (KZ - 1) / 2) ? mz : mz - KZ;
            float fx = (float)smx, fy = (float)smy, fz = (float)smz;
            float mv0 = fx*s_inv[0] + fy*s_inv[1] + fz*s_inv[2];
            float mv1 = fx*s_inv[3] + fy*s_inv[4] + fz*s_inv[5];
            float mv2 = fx*s_inv[6] + fy*s_inv[7] + fz*s_inv[8];
            float m2 = mv0*mv0 + mv1*mv1 + mv2*mv2;
            if (m2 > 0.0f) {
                const float pi2_over_a2 = (float)(9.869604401089358 / (ALPHAD * ALPHAD));
                float green = __expf(-pi2_over_a2 * m2) / m2;
                float B = s_bmod[mx] * s_bmod[14 + my] * s_bmod[29 + mz];
                contrib = green * B * (fr*fr + fi*fi);
            }
        }
        __syncthreads();   // sred reuse safety
        if ((tid & 15) == 0) sred[tid >> 4] = contrib;
        __syncthreads();
        if (tid == 0) {
            float s = 0.0f;
            #pragma unroll
            for (int w = 0; w < 64; w++) s += sred[w];
            if (s != 0.0f) atomicAdd(&g_erec, (double)s);
        }
    }
    // no barrier needed before direct (independent inputs)

    // ------- phase 5: direct space triangle tile (thread = i x j-quarter) -------
    // gid is block-uniform: all __syncthreads/shfl below are block/warp-uniform.
    if (gid < NDIRBLK) {
        int L = gid, bx = 0;
        while (L >= 16 - bx) { L -= 16 - bx; bx++; }
        int by = bx + L;

        int il  = tid & 255;           // i_local
        int qtr = tid >> 8;            // j quarter 0..3
        int i   = bx * 256 + il;
        int j0  = by * 256;
        __syncthreads();               // protect sj reuse across phases
        if (tid < 256) {
            int jg = j0 + tid;
            sj[tid] = make_float4(pos[3*jg], pos[3*jg+1], pos[3*jg+2], chg[jg]);
        }
        __syncthreads();
        float Lx = box[0], Ly = box[4], Lz = box[8];
        float iLx = 1.0f / Lx, iLy = 1.0f / Ly, iLz = 1.0f / Lz;
        float xi = pos[3*i], yi = pos[3*i+1], zi = pos[3*i+2], qi = chg[i];
        float acc = 0.0f;
        int jbase = qtr * 64;
        if (bx == by) {
            #pragma unroll 8
            for (int jj = 0; jj < 64; jj++) {
                float4 p = sj[jbase + jj];
                float dx = xi - p.x; dx -= Lx * rintf(dx * iLx);
                float dy = yi - p.y; dy -= Ly * rintf(dy * iLy);
                float dz = zi - p.z; dz -= Lz * rintf(dz * iLz);
                float r2 = fmaf(dx, dx, fmaf(dy, dy, dz * dz));
                if (r2 < CUT2 && (jbase + jj) != il) {
                    float rinv = rsqrtf(r2);
                    acc += qi * p.w * erfcf(ALPHAF * r2 * rinv) * rinv;
                }
            }
        } else {
            #pragma unroll 8
            for (int jj = 0; jj < 64; jj++) {
                float4 p = sj[jbase + jj];
                float dx = xi - p.x; dx -= Lx * rintf(dx * iLx);
                float dy = yi - p.y; dy -= Ly * rintf(dy * iLy);
                float dz = zi - p.z; dz -= Lz * rintf(dz * iLz);
                float r2 = fmaf(dx, dx, fmaf(dy, dy, dz * dz));
                if (r2 < CUT2) {
                    float rinv = rsqrtf(r2);
                    acc += qi * p.w * erfcf(ALPHAF * r2 * rinv) * rinv;
                }
            }
            acc *= 2.0f;   // unordered off-diagonal pairs counted once
        }
        #pragma unroll
        for (int o = 16; o; o >>= 1) acc += __shfl_xor_sync(0xffffffffu, acc, o);
        if (lane == 0) sred[wid] = acc;
        __syncthreads();
        if (tid == 0) {
            float s = 0.0f;
            #pragma unroll
            for (int w = 0; w < 32; w++) s += sred[w];
            atomicAdd(&g_edir, (double)s);
        }
    }
    gridbar();   // all energy terms complete

    // ---------------- final combine ----------------
    if (gid == 0 && tid == 0) {
        const double SQRT_PI = 1.7724538509055159;
        double edir  = 0.5 * COULOMB * g_edir;
        double erec  = COULOMB / (2.0 * 3.141592653589793 * s_Vd) * g_erec;
        double eself = -COULOMB * ALPHAD / SQRT_PI * g_q2;
        out[0] = (float)(edir - (erec + eself));
    }
}

extern "C" void kernel_launch(void* const* d_in, const int* in_sizes, int n_in,
                              void* d_out, int out_size) {
    int ip = 0, ic = 1, ib = 2;
    for (int k = 0; k < n_in; k++) {
        if (in_sizes[k] == NATOMS * 3) ip = k;
        else if (in_sizes[k] == NATOMS) ic = k;
        else if (in_sizes[k] == 9)      ib = k;
    }
    const float* pos = (const float*)d_in[ip];
    const float* chg = (const float*)d_in[ic];
    const float* box = (const float*)d_in[ib];
    float* out = (float*)d_out;

    k_all<<<NBLK, NTHR>>>(pos, chg, box, out);
}

// round 10
// speedup vs baseline: 1.6495x; 1.0713x over previous
#include <cuda_runtime.h>
#include <math.h>

#define NATOMS 4096
#define KX 14
#define KY 15
#define KZ 16
#define NGRID (KX*KY*KZ)          /* 3360 */
#define KYZ (KY*KZ)               /* 240 */
#define ALPHAF 4.985823141035867f
#define ALPHAD 4.985823141035867
#define COULOMB 138.935
#define CUT2 0.25f
#define NBLK 148                  /* one block per SM: all resident, spin-safe */
#define NDIRBLK 136               /* 16*17/2 triangle tiles */
#define NTHR 1024

// -------- device scratch (static, allocation-free) --------
__device__ float  g_grid[NGRID];
__device__ float2 g_cz[NGRID];
__device__ float2 g_cy[NGRID];
__device__ double g_edir, g_erec, g_q2;
__device__ unsigned int g_bar_count;   // zero-init
__device__ unsigned int g_bar_gen;     // zero-init, grows across replays

// -------- device-wide barrier (all NBLK blocks resident) --------
__device__ __forceinline__ void gridbar() {
    __syncthreads();
    if (threadIdx.x == 0) {
        __threadfence();
        unsigned gen = *(volatile unsigned*)&g_bar_gen;
        if (atomicAdd(&g_bar_count, 1u) == NBLK - 1) {
            *(volatile unsigned*)&g_bar_count = 0;
            __threadfence();
            *(volatile unsigned*)&g_bar_gen = gen + 1;
        } else {
            while (*(volatile unsigned*)&g_bar_gen == gen) __nanosleep(32);
        }
        __threadfence();
    }
    __syncthreads();
}

// -------- fast erfc (Abramowitz-Stegun 7.1.26, abs err <= 1.5e-7) --------
__device__ __forceinline__ float erfc_fast(float x) {
    float t = __fdividef(1.0f, fmaf(0.3275911f, x, 1.0f));
    float p = fmaf(fmaf(fmaf(fmaf(1.061405429f, t, -1.453152027f),
                             t, 1.421413741f),
                        t, -0.284496736f),
                   t, 0.254829592f) * t;
    return p * __expf(-x * x);
}

// -------- order-5 cardinal B-spline: d[k] = M5(w+k), w in [0,1) --------
__device__ __forceinline__ void bspline5(float w, float d[5]) {
    float b2_0 = w, b2_1 = 1.0f - w;
    float b3_0 = 0.5f * w * b2_0;
    float b3_1 = 0.5f * ((w + 1.0f) * b2_1 + (2.0f - w) * b2_0);
    float b3_2 = 0.5f * (1.0f - w) * b2_1;
    const float i3 = 1.0f / 3.0f;
    float b4_0 = i3 * w * b3_0;
    float b4_1 = i3 * ((w + 1.0f) * b3_1 + (3.0f - w) * b3_0);
    float b4_2 = i3 * ((w + 2.0f) * b3_2 + (2.0f - w) * b3_1);
    float b4_3 = i3 * (1.0f - w) * b3_2;
    d[0] = 0.25f * w * b4_0;
    d[1] = 0.25f * ((w + 1.0f) * b4_1 + (4.0f - w) * b4_0);
    d[2] = 0.25f * ((w + 2.0f) * b4_2 + (3.0f - w) * b4_1);
    d[3] = 0.25f * ((w + 3.0f) * b4_3 + (2.0f - w) * b4_2);
    d[4] = 0.25f * (1.0f - w) * b4_3;
}

// 16-lane sum reduce. MUST be executed by all 32 lanes of every warp that
// reaches it (warp-collective); callers pass 0 for inactive lanes.
__device__ __forceinline__ float hred(float v) {
    v += __shfl_xor_sync(0xffffffffu, v, 8);
    v += __shfl_xor_sync(0xffffffffu, v, 4);
    v += __shfl_xor_sync(0xffffffffu, v, 2);
    v += __shfl_xor_sync(0xffffffffu, v, 1);
    return v;
}

__global__ void __launch_bounds__(NTHR) k_all(const float* __restrict__ pos,
                                              const float* __restrict__ chg,
                                              const float* __restrict__ box,
                                              float* __restrict__ out) {
    __shared__ float  s_twc[45], s_tws[45], s_bmod[45];
    __shared__ float  s_inv[9];
    __shared__ double s_Vd;
    __shared__ float4 sj[256];
    __shared__ float  sred[64];

    const int gid = blockIdx.x;
    const int tid = threadIdx.x;
    const int lane = tid & 31;
    const int wid = tid >> 5;

    // ---------------- phase 0: zero mesh + tables ----------------
    {
        int gtid = gid * NTHR + tid;
        if (gtid < NGRID) g_grid[gtid] = 0.0f;
        if (gid == 0 && tid == 0) { g_edir = 0.0; g_erec = 0.0; g_q2 = 0.0; }
        if (tid < 45) {
            int K, m;
            if      (tid < KX)      { K = KX; m = tid; }
            else if (tid < KX + KY) { K = KY; m = tid - KX; }
            else                    { K = KZ; m = tid - KX - KY; }
            float s, c;
            sincospif(2.0f * (float)m / (float)K, &s, &c);
            s_twc[tid] = c; s_tws[tid] = s;
            const float Mv[4] = {1.0f/24.0f, 11.0f/24.0f, 11.0f/24.0f, 1.0f/24.0f};
            float dr = 0.0f, di = 0.0f;
            #pragma unroll
            for (int k = 0; k < 4; k++) {
                int p = (m * k) % K;
                float ss, cc;
                sincospif(2.0f * (float)p / (float)K, &ss, &cc);
                dr += Mv[k] * cc; di += Mv[k] * ss;
            }
            float d2 = dr*dr + di*di;
            s_bmod[tid] = (d2 < 1e-7f) ? 0.0f : 1.0f / d2;
        }
        if (tid == 64) {   // separate warp from table warp
            double b00 = box[0], b01 = box[1], b02 = box[2];
            double b10 = box[3], b11 = box[4], b12 = box[5];
            double b20 = box[6], b21 = box[7], b22 = box[8];
            double c00 =  (b11*b22 - b12*b21);
            double c01 = -(b10*b22 - b12*b20);
            double c02 =  (b10*b21 - b11*b20);
            double det = b00*c00 + b01*c01 + b02*c02;
            double id = 1.0 / det;
            s_inv[0] = (float)(c00 * id);
            s_inv[1] = (float)(-(b01*b22 - b02*b21) * id);
            s_inv[2] = (float)( (b01*b12 - b02*b11) * id);
            s_inv[3] = (float)(c01 * id);
            s_inv[4] = (float)( (b00*b22 - b02*b20) * id);
            s_inv[5] = (float)(-(b00*b12 - b02*b10) * id);
            s_inv[6] = (float)(c02 * id);
            s_inv[7] = (float)(-(b00*b21 - b01*b20) * id);
            s_inv[8] = (float)( (b00*b11 - b01*b10) * id);
            s_Vd = fabs(det);
        }
    }
    gridbar();   // mesh zeroed, tables ready

    // ------- phase 1: spread (thread = atom x x-slice) + q^2 -------
    {
        float q2c = 0.0f;
        int k  = tid / 5;              // atom ordinal within block
        int aa = tid - 5 * k;          // x-slice 0..4
        int a  = gid + NBLK * k;
        if (a < NATOMS) {
            float q = chg[a];
            if (aa == 0) q2c = q * q;
            float px = pos[3*a], py = pos[3*a+1], pz = pos[3*a+2];
            const int Ks[3] = {KX, KY, KZ};
            float wts[3][5];
            int   idx[3][5];
            #pragma unroll
            for (int d = 0; d < 3; d++) {
                float f = px*s_inv[0+d] + py*s_inv[3+d] + pz*s_inv[6+d];
                f -= floorf(f);
                if (f >= 1.0f) f = 0.0f;
                float u  = f * (float)Ks[d];
                float fl = floorf(u);
                int base = (int)fl;
                if (base >= Ks[d]) { base = Ks[d] - 1; fl = (float)base; }
                float w = u - fl;
                bspline5(w, wts[d]);
                #pragma unroll
                for (int kk = 0; kk < 5; kk++) {
                    int ii = base - kk;
                    if (ii < 0) ii += Ks[d];
                    idx[d][kk] = ii;
                }
            }
            int offx = idx[0][aa] * KYZ;
            float wx = q * wts[0][aa];
            #pragma unroll
            for (int bb = 0; bb < 5; bb++) {
                float wab = wx * wts[1][bb];
                int off = offx + idx[1][bb] * KZ;
                #pragma unroll
                for (int cc = 0; cc < 5; cc++)
                    atomicAdd(&g_grid[off + idx[2][cc]], wab * wts[2][cc]);
            }
        }
        // full-warp reduce (all lanes participate)
        #pragma unroll
        for (int o = 16; o; o >>= 1) q2c += __shfl_xor_sync(0xffffffffu, q2c, o);
        if (lane == 0) sred[wid] = q2c;
        __syncthreads();
        if (tid == 0) {
            float s = 0.0f;
            #pragma unroll
            for (int w = 0; w < 32; w++) s += sred[w];
            if (s != 0.0f) atomicAdd(&g_q2, (double)s);
        }
    }
    gridbar();   // mesh + q2 complete

    // ------- phase 2: DFT over z (16-lane group per output) -------
    {
        int grp = tid >> 4, l = tid & 15;
        int o = gid + NBLK * grp;             // bijective over [0, 148*64)
        bool ok = (o < NGRID);
        float vc = 0.0f, vs = 0.0f;
        if (ok) {
            int gx = o / KYZ, r = o % KYZ, gy = r / KZ, mz = r % KZ;
            float v = g_grid[gx * KYZ + gy * KZ + l];    // l = gz
            int p = (mz * l) & (KZ - 1);
            vc =  v * s_twc[29 + p];
            vs = -v * s_tws[29 + p];
        }
        float fr = hred(vc);                  // warp-collective: all lanes
        float fi = hred(vs);
        if (ok && l == 0) g_cz[o] = make_float2(fr, fi);
    }
    gridbar();

    // ------- phase 3: DFT over y -------
    {
        int grp = tid >> 4, l = tid & 15;
        int o = gid + NBLK * grp;
        bool ok = (o < NGRID);
        float fr = 0.0f, fi = 0.0f;
        if (ok && l < KY) {
            int gx = o / KYZ, r = o % KYZ, my = r / KZ, mz = r % KZ;
            float2 cv = g_cz[gx * KYZ + l * KZ + mz];   // l = gy
            int p = (my * l) % KY;
            float c = s_twc[14 + p], s = s_tws[14 + p];
            fr = cv.x * c + cv.y * s;
            fi = cv.y * c - cv.x * s;
        }
        fr = hred(fr); fi = hred(fi);         // warp-collective: all lanes
        if (ok && l == 0) g_cy[o] = make_float2(fr, fi);
    }
    gridbar();

    // ------- phase 4: DFT over x + green/B reduce -------
    {
        int grp = tid >> 4, l = tid & 15;
        int o = gid + NBLK * grp;
        bool ok = (o < NGRID);
        float fr = 0.0f, fi = 0.0f;
        int mx = 0, my = 0, mz = 0;
        if (ok) {
            mx = o / KYZ; int r = o % KYZ; my = r / KZ; mz = r % KZ;
            if (l < KX) {
                float2 cv = g_cy[l * KYZ + my * KZ + mz];   // l = gx
                int p = (mx * l) % KX;
                float c = s_twc[p], s = s_tws[p];
                fr = cv.x * c + cv.y * s;
                fi = cv.y * c - cv.x * s;
            }
        }
        fr = hred(fr); fi = hred(fi);         // warp-collective: all lanes
        float contrib = 0.0f;
        if (ok && l == 0) {
            int smx = (mx <= (KX - 1) / 2) ? mx : mx - KX;
            int smy = (my <= (KY - 1) / 2) ? my : my - KY;
            int smz = (mz <= (KZ - 1) / 2) ? mz : mz - KZ;
            float fx = (float)smx, fy = (float)smy, fz = (float)smz;
            float mv0 = fx*s_inv[0] + fy*s_inv[1] + fz*s_inv[2];
            float mv1 = fx*s_inv[3] + fy*s_inv[4] + fz*s_inv[5];
            float mv2 = fx*s_inv[6] + fy*s_inv[7] + fz*s_inv[8];
            float m2 = mv0*mv0 + mv1*mv1 + mv2*mv2;
            if (m2 > 0.0f) {
                const float pi2_over_a2 = (float)(9.869604401089358 / (ALPHAD * ALPHAD));
                float green = __expf(-pi2_over_a2 * m2) / m2;
                float B = s_bmod[mx] * s_bmod[14 + my] * s_bmod[29 + mz];
                contrib = green * B * (fr*fr + fi*fi);
            }
        }
        __syncthreads();   // sred reuse safety
        if ((tid & 15) == 0) sred[tid >> 4] = contrib;
        __syncthreads();
        if (tid == 0) {
            float s = 0.0f;
            #pragma unroll
            for (int w = 0; w < 64; w++) s += sred[w];
            if (s != 0.0f) atomicAdd(&g_erec, (double)s);
        }
    }
    // no barrier needed before direct (independent inputs)

    // ------- phase 5: direct space triangle tile (thread = i x j-quarter) -------
    // gid is block-uniform: all __syncthreads/shfl below are block/warp-uniform.
    if (gid < NDIRBLK) {
        int L = gid, bx = 0;
        while (L >= 16 - bx) { L -= 16 - bx; bx++; }
        int by = bx + L;

        int il  = tid & 255;           // i_local
        int qtr = tid >> 8;            // j quarter 0..3
        int i   = bx * 256 + il;
        int j0  = by * 256;
        __syncthreads();               // protect sj reuse across phases
        if (tid < 256) {
            int jg = j0 + tid;
            sj[tid] = make_float4(pos[3*jg], pos[3*jg+1], pos[3*jg+2], chg[jg]);
        }
        __syncthreads();
        float Lx = box[0], Ly = box[4], Lz = box[8];
        float iLx = 1.0f / Lx, iLy = 1.0f / Ly, iLz = 1.0f / Lz;
        float xi = pos[3*i], yi = pos[3*i+1], zi = pos[3*i+2], qi = chg[i];
        float acc = 0.0f;
        int jbase = qtr * 64;
        if (bx == by) {
            #pragma unroll 8
            for (int jj = 0; jj < 64; jj++) {
                float4 p = sj[jbase + jj];
                float dx = xi - p.x; dx -= Lx * rintf(dx * iLx);
                float dy = yi - p.y; dy -= Ly * rintf(dy * iLy);
                float dz = zi - p.z; dz -= Lz * rintf(dz * iLz);
                float r2 = fmaf(dx, dx, fmaf(dy, dy, dz * dz));
                if (r2 < CUT2 && (jbase + jj) != il) {
                    float rinv = rsqrtf(r2);
                    float x = ALPHAF * r2 * rinv;          // alpha * r
                    acc = fmaf(qi * p.w * erfc_fast(x), rinv, acc);
                }
            }
        } else {
            #pragma unroll 8
            for (int jj = 0; jj < 64; jj++) {
                float4 p = sj[jbase + jj];
                float dx = xi - p.x; dx -= Lx * rintf(dx * iLx);
                float dy = yi - p.y; dy -= Ly * rintf(dy * iLy);
                float dz = zi - p.z; dz -= Lz * rintf(dz * iLz);
                float r2 = fmaf(dx, dx, fmaf(dy, dy, dz * dz));
                if (r2 < CUT2) {
                    float rinv = rsqrtf(r2);
                    float x = ALPHAF * r2 * rinv;
                    acc = fmaf(qi * p.w * erfc_fast(x), rinv, acc);
                }
            }
            acc *= 2.0f;   // unordered off-diagonal pairs counted once
        }
        #pragma unroll
        for (int o = 16; o; o >>= 1) acc += __shfl_xor_sync(0xffffffffu, acc, o);
        if (lane == 0) sred[wid] = acc;
        __syncthreads();
        if (tid == 0) {
            float s = 0.0f;
            #pragma unroll
            for (int w = 0; w < 32; w++) s += sred[w];
            atomicAdd(&g_edir, (double)s);
        }
    }
    gridbar();   // all energy terms complete

    // ---------------- final combine ----------------
    if (gid == 0 && tid == 0) {
        const double SQRT_PI = 1.7724538509055159;
        double edir  = 0.5 * COULOMB * g_edir;
        double erec  = COULOMB / (2.0 * 3.141592653589793 * s_Vd) * g_erec;
        double eself = -COULOMB * ALPHAD / SQRT_PI * g_q2;
        out[0] = (float)(edir - (erec + eself));
    }
}

extern "C" void kernel_launch(void* const* d_in, const int* in_sizes, int n_in,
                              void* d_out, int out_size) {
    int ip = 0, ic = 1, ib = 2;
    for (int k = 0; k < n_in; k++) {
        if (in_sizes[k] == NATOMS * 3) ip = k;
        else if (in_sizes[k] == NATOMS) ic = k;
        else if (in_sizes[k] == 9)      ib = k;
    }
    const float* pos = (const float*)d_in[ip];
    const float* chg = (const float*)d_in[ic];
    const float* box = (const float*)d_in[ib];
    float* out = (float*)d_out;

    k_all<<<NBLK, NTHR>>>(pos, chg, box, out);
}